// round 1
// baseline (speedup 1.0000x reference)
#include <cuda_runtime.h>

#define NN 512
#define CC 64
#define HH 256
#define EPSF 1e-5f

// Scratch tables (device globals: no allocation allowed in kernel_launch)
__device__ float g_RA [NN*HH];
__device__ float g_RB [NN*HH];
__device__ float g_A1M[NN*HH];
__device__ float g_A2P[NN*HH];
__device__ float g_B1P[NN*HH];
__device__ float g_B2M[NN*HH];

// ---------------------------------------------------------------------------
// Stage 1: six 512x64 @ 64x256 GEMMs + shifts folded into row tables.
//   A0[i]=xl_i@W1[0:64], B0[j]=xr_j@W1[64:128], A1=xl@W1[128:192],
//   B1=xr@W1[192:256],   A2=xl@W1[256:320],    B2=xr@W1[320:384]
//   A1m[i]=A1[i-1] (0 at i=0), A2p[i]=A2[i+1] (0 at 511),
//   B1p[j]=B1[j+1] (0 at 511), B2m[j]=B2[j-1] (0 at 0)
//   RA[i]=A0+b1+A1m+A2p,  RB[j]=B0+B1p+B2m
// ---------------------------------------------------------------------------
#define PR_ROWS 4
__global__ __launch_bounds__(256) void precompute_kernel(
    const float* __restrict__ xl, const float* __restrict__ xr,
    const float* __restrict__ W1, const float* __restrict__ b1)
{
    __shared__ float sxl[PR_ROWS + 2][CC];
    __shared__ float sxr[PR_ROWS + 2][CC];
    const int h  = threadIdx.x;          // hidden channel 0..255
    const int i0 = blockIdx.x * PR_ROWS;

    for (int k = h; k < (PR_ROWS + 2) * CC; k += 256) {
        int r = k >> 6, f = k & 63;
        int gi = i0 - 1 + r;
        bool ok = (gi >= 0) && (gi < NN);
        sxl[r][f] = ok ? xl[gi * CC + f] : 0.f;
        sxr[r][f] = ok ? xr[gi * CC + f] : 0.f;
    }
    __syncthreads();

    float a0[PR_ROWS], a1[PR_ROWS], a2[PR_ROWS];
    float b0[PR_ROWS], bp[PR_ROWS], bm[PR_ROWS];
#pragma unroll
    for (int r = 0; r < PR_ROWS; r++) {
        a0[r] = a1[r] = a2[r] = 0.f;
        b0[r] = bp[r] = bm[r] = 0.f;
    }

#pragma unroll 4
    for (int f = 0; f < CC; f++) {
        float wa0 = W1[(0 * CC + f) * HH + h];
        float wb0 = W1[(1 * CC + f) * HH + h];
        float wa1 = W1[(2 * CC + f) * HH + h];
        float wb1 = W1[(3 * CC + f) * HH + h];
        float wa2 = W1[(4 * CC + f) * HH + h];
        float wb2 = W1[(5 * CC + f) * HH + h];
#pragma unroll
        for (int r = 0; r < PR_ROWS; r++) {
            a0[r] = fmaf(sxl[r + 1][f], wa0, a0[r]);   // xl[i]
            a1[r] = fmaf(sxl[r    ][f], wa1, a1[r]);   // xl[i-1] (zero-padded)
            a2[r] = fmaf(sxl[r + 2][f], wa2, a2[r]);   // xl[i+1]
            b0[r] = fmaf(sxr[r + 1][f], wb0, b0[r]);   // xr[j]
            bp[r] = fmaf(sxr[r + 2][f], wb1, bp[r]);   // xr[j+1]
            bm[r] = fmaf(sxr[r    ][f], wb2, bm[r]);   // xr[j-1]
        }
    }

    const float bb = b1[h];
#pragma unroll
    for (int r = 0; r < PR_ROWS; r++) {
        int i = i0 + r;
        g_A1M[i * HH + h] = a1[r];
        g_A2P[i * HH + h] = a2[r];
        g_RA [i * HH + h] = a0[r] + bb + a1[r] + a2[r];
        g_B1P[i * HH + h] = bp[r];
        g_B2M[i * HH + h] = bm[r];
        g_RB [i * HH + h] = b0[r] + bp[r] + bm[r];
    }
}

// ---------------------------------------------------------------------------
// Shared epilogue: LayerNorm + CELU + dot(W2), warp-collective.
// Lane owns 8 channels: {4*lane..4*lane+3} and {128+4*lane..128+4*lane+3}.
// ---------------------------------------------------------------------------
__device__ __forceinline__ float ln_celu_dot(
    const float* s, const float* gm, const float* bt, const float* w2)
{
    float sum = ((s[0] + s[1]) + (s[2] + s[3])) + ((s[4] + s[5]) + (s[6] + s[7]));
    float sq0 = fmaf(s[0], s[0], s[1] * s[1]);
    sq0 = fmaf(s[2], s[2], fmaf(s[3], s[3], sq0));
    float sq1 = fmaf(s[4], s[4], s[5] * s[5]);
    sq1 = fmaf(s[6], s[6], fmaf(s[7], s[7], sq1));
    float sq = sq0 + sq1;
#pragma unroll
    for (int off = 16; off > 0; off >>= 1) {
        sum += __shfl_xor_sync(0xffffffffu, sum, off);
        sq  += __shfl_xor_sync(0xffffffffu, sq,  off);
    }
    float mu  = sum * (1.f / 256.f);
    float var = fmaf(sq, 1.f / 256.f, -mu * mu);
    float rs  = rsqrtf(var + EPSF);
    float nm  = -mu * rs;
    float acc = 0.f;
#pragma unroll
    for (int k = 0; k < 8; k++) {
        float hn = fmaf(fmaf(s[k], rs, nm), gm[k], bt[k]);
        float e  = __expf(fminf(hn, 0.f)) - 1.f;   // 0 for hn>0, expm1 for hn<=0
        float v  = fmaxf(hn, 0.f) + e;             // CELU(alpha=1)
        acc = fmaf(v, w2[k], acc);
    }
#pragma unroll
    for (int off = 16; off > 0; off >>= 1)
        acc += __shfl_xor_sync(0xffffffffu, acc, off);
    return acc;
}

// ---------------------------------------------------------------------------
// Stage 2: main pairwise kernel. Block = 16x16 tile of cells, warp per cell.
// Interior formula only: s = RA[i] + RB[j]. Borders fixed by fixup_kernel.
// ---------------------------------------------------------------------------
__global__ __launch_bounds__(256) void pair_main_kernel(
    const float* __restrict__ gamma, const float* __restrict__ beta,
    const float* __restrict__ W2, const float* __restrict__ b2,
    float* __restrict__ out)
{
    __shared__ float4 sA[16 * 64];   // 16 RA rows, 256 f32 each
    __shared__ float4 sB[16 * 64];   // 16 RB rows
    __shared__ float  sOut[256];

    const int t  = threadIdx.x;
    const int i0 = blockIdx.y * 16, j0 = blockIdx.x * 16;

    const float4* gA = reinterpret_cast<const float4*>(g_RA) + i0 * 64;
    const float4* gB = reinterpret_cast<const float4*>(g_RB) + j0 * 64;
#pragma unroll
    for (int k = 0; k < 4; k++) {
        sA[t + 256 * k] = gA[t + 256 * k];
        sB[t + 256 * k] = gB[t + 256 * k];
    }

    const int lane = t & 31, w = t >> 5;
    const int c0 = 4 * lane, c1 = 128 + 4 * lane;

    float gm[8], bt[8], w2r[8];
    {
        float4 v;
        v = *reinterpret_cast<const float4*>(gamma + c0); gm[0]=v.x; gm[1]=v.y; gm[2]=v.z; gm[3]=v.w;
        v = *reinterpret_cast<const float4*>(gamma + c1); gm[4]=v.x; gm[5]=v.y; gm[6]=v.z; gm[7]=v.w;
        v = *reinterpret_cast<const float4*>(beta  + c0); bt[0]=v.x; bt[1]=v.y; bt[2]=v.z; bt[3]=v.w;
        v = *reinterpret_cast<const float4*>(beta  + c1); bt[4]=v.x; bt[5]=v.y; bt[6]=v.z; bt[7]=v.w;
        v = *reinterpret_cast<const float4*>(W2    + c0); w2r[0]=v.x; w2r[1]=v.y; w2r[2]=v.z; w2r[3]=v.w;
        v = *reinterpret_cast<const float4*>(W2    + c1); w2r[4]=v.x; w2r[5]=v.y; w2r[6]=v.z; w2r[7]=v.w;
    }
    const float bb2 = b2[0];
    __syncthreads();

#pragma unroll 2
    for (int k = 0; k < 32; k++) {
        int cidx = k * 8 + w;             // 0..255 cell within tile
        int li = cidx >> 4, lj = cidx & 15;
        float4 a0  = sA[li * 64 + lane];
        float4 a1  = sA[li * 64 + 32 + lane];
        float4 bv0 = sB[lj * 64 + lane];
        float4 bv1 = sB[lj * 64 + 32 + lane];
        float s[8];
        s[0] = a0.x + bv0.x; s[1] = a0.y + bv0.y;
        s[2] = a0.z + bv0.z; s[3] = a0.w + bv0.w;
        s[4] = a1.x + bv1.x; s[5] = a1.y + bv1.y;
        s[6] = a1.z + bv1.z; s[7] = a1.w + bv1.w;

        float y = ln_celu_dot(s, gm, bt, w2r);
        if (lane == 0) sOut[cidx] = y + bb2;
    }
    __syncthreads();
    out[(i0 + (t >> 4)) * NN + j0 + (t & 15)] = sOut[t];
}

// ---------------------------------------------------------------------------
// Stage 3: border fixup. 2048 warps, one per border cell (corners done twice
// with identical values). Full masked formula:
//   s = RA+RB - [i==0||j==511]*(A1m+B1p) - [i==511||j==0]*(A2p+B2m)
// ---------------------------------------------------------------------------
__global__ __launch_bounds__(256) void fixup_kernel(
    const float* __restrict__ gamma, const float* __restrict__ beta,
    const float* __restrict__ W2, const float* __restrict__ b2,
    float* __restrict__ out)
{
    const int gw   = (blockIdx.x * 256 + threadIdx.x) >> 5;  // 0..2047
    const int lane = threadIdx.x & 31;
    const int side = gw >> 9, pos = gw & 511;
    int i, j;
    if      (side == 0) { i = 0;      j = pos; }
    else if (side == 1) { i = NN - 1; j = pos; }
    else if (side == 2) { i = pos;    j = 0; }
    else                { i = pos;    j = NN - 1; }

    const float cu = (i == 0 || j == NN - 1) ? 1.f : 0.f;
    const float cd = (i == NN - 1 || j == 0) ? 1.f : 0.f;
    const int c0 = 4 * lane, c1 = 128 + 4 * lane;

    float s[8], gm[8], bt[8], w2r[8];
#pragma unroll
    for (int k = 0; k < 8; k++) {
        int c = (k < 4) ? (c0 + k) : (c1 + k - 4);
        float ra  = g_RA [i * HH + c], rb  = g_RB [j * HH + c];
        float a1v = g_A1M[i * HH + c], b1p = g_B1P[j * HH + c];
        float a2v = g_A2P[i * HH + c], b2m = g_B2M[j * HH + c];
        s[k] = ra + rb - cu * (a1v + b1p) - cd * (a2v + b2m);
        gm[k] = gamma[c]; bt[k] = beta[c]; w2r[k] = W2[c];
    }
    float y = ln_celu_dot(s, gm, bt, w2r);
    if (lane == 0) out[i * NN + j] = y + b2[0];
}

// ---------------------------------------------------------------------------
extern "C" void kernel_launch(void* const* d_in, const int* in_sizes, int n_in,
                              void* d_out, int out_size)
{
    const float* xl    = (const float*)d_in[0];
    const float* xr    = (const float*)d_in[1];
    const float* W1    = (const float*)d_in[2];
    const float* b1    = (const float*)d_in[3];
    const float* gamma = (const float*)d_in[4];
    const float* beta  = (const float*)d_in[5];
    const float* W2    = (const float*)d_in[6];
    const float* b2    = (const float*)d_in[7];
    float* out = (float*)d_out;

    precompute_kernel<<<NN / PR_ROWS, 256>>>(xl, xr, W1, b1);
    dim3 grid(NN / 16, NN / 16);
    pair_main_kernel<<<grid, 256>>>(gamma, beta, W2, b2, out);
    fixup_kernel<<<(4 * NN * 32) / 256, 256>>>(gamma, beta, W2, b2, out);
}

// round 2
// speedup vs baseline: 1.2385x; 1.2385x over previous
#include <cuda_runtime.h>

#define NN 512
#define CC 64
#define HH 256
#define EPSF 1e-5f

typedef unsigned long long u64;

// ---------------- packed f32x2 helpers (sm_100+) ----------------
__device__ __forceinline__ u64 pk(float lo, float hi) {
    u64 r; asm("mov.b64 %0,{%1,%2};" : "=l"(r) : "f"(lo), "f"(hi)); return r;
}
__device__ __forceinline__ void unpk(u64 v, float& lo, float& hi) {
    asm("mov.b64 {%0,%1},%2;" : "=f"(lo), "=f"(hi) : "l"(v));
}
__device__ __forceinline__ u64 add2(u64 a, u64 b) {
    u64 r; asm("add.rn.f32x2 %0,%1,%2;" : "=l"(r) : "l"(a), "l"(b)); return r;
}
__device__ __forceinline__ u64 mul2(u64 a, u64 b) {
    u64 r; asm("mul.rn.f32x2 %0,%1,%2;" : "=l"(r) : "l"(a), "l"(b)); return r;
}
__device__ __forceinline__ u64 fma2(u64 a, u64 b, u64 c) {
    u64 r; asm("fma.rn.f32x2 %0,%1,%2,%3;" : "=l"(r) : "l"(a), "l"(b), "l"(c)); return r;
}
__device__ __forceinline__ float ex2f(float x) {
    float r; asm("ex2.approx.f32 %0,%1;" : "=f"(r) : "f"(x)); return r;
}

// ---------------- scratch (device globals; no allocs allowed) ----------------
__device__ float g_T[2][NN][768];   // T_A = xl@[W0|W2|W4], T_B = xr@[W1|W3|W5]
__device__ float g_RA [NN*HH];
__device__ float g_RB [NN*HH];
__device__ float g_A1M[NN*HH];
__device__ float g_A2P[NN*HH];
__device__ float g_B1P[NN*HH];
__device__ float g_B2M[NN*HH];
__device__ float g_SA[NN];
__device__ float g_SB[NN];

// ---------------------------------------------------------------------------
// Stage 1: tiled GEMM.  z=0: T_A[i,n] = sum_f xl[i,f]*W1[(2*sel+0)*64+f][h0+n']
//                       z=1: T_B with blocks 1,3,5.  M=512, N=768, K=64.
// 64x64 tiles, K=64 entirely in smem, 4x4 microtile per thread.
// ---------------------------------------------------------------------------
__global__ __launch_bounds__(256) void gemm_pre_kernel(
    const float* __restrict__ xl, const float* __restrict__ xr,
    const float* __restrict__ W1)
{
    __shared__ float Xs[64][68];  // [k][m], padded
    __shared__ float Ws[64][68];  // [k][n], padded

    const int z  = blockIdx.z;
    const float* X = z ? xr : xl;
    const int m0 = blockIdx.x * 64;
    const int n0 = blockIdx.y * 64;
    const int sel = n0 >> 8;            // which hidden-256 block (0..2)
    const int h0  = n0 & 255;
    const float* Wbase = W1 + ((2 * sel + z) * 64) * HH + h0;  // Wbase[f*HH + n]

    const int t = threadIdx.x;
    {   // load X transposed: Xs[f][i] = X[(m0+i)*64 + f]
        int f = t & 63, i0 = t >> 6;
#pragma unroll
        for (int ii = 0; ii < 64; ii += 4)
            Xs[f][i0 + ii] = X[(m0 + i0 + ii) * CC + f];
    }
    {   // load W: Ws[f][n] = Wbase[f*HH + n]
        int n = t & 63, f0 = t >> 6;
#pragma unroll
        for (int ff = 0; ff < 64; ff += 4)
            Ws[f0 + ff][n] = Wbase[(f0 + ff) * HH + n];
    }
    __syncthreads();

    const int tx = t & 15, ty = t >> 4;   // n = n0+4*tx.., m = m0+4*ty..
    float acc[4][4] = {};
#pragma unroll 16
    for (int k = 0; k < 64; k++) {
        float4 xa = *reinterpret_cast<const float4*>(&Xs[k][4 * ty]);
        float4 wb = *reinterpret_cast<const float4*>(&Ws[k][4 * tx]);
        float xr4[4] = {xa.x, xa.y, xa.z, xa.w};
        float wr4[4] = {wb.x, wb.y, wb.z, wb.w};
#pragma unroll
        for (int r = 0; r < 4; r++)
#pragma unroll
            for (int c = 0; c < 4; c++)
                acc[r][c] = fmaf(xr4[r], wr4[c], acc[r][c]);
    }
#pragma unroll
    for (int r = 0; r < 4; r++) {
        float4 v = make_float4(acc[r][0], acc[r][1], acc[r][2], acc[r][3]);
        *reinterpret_cast<float4*>(&g_T[z][m0 + 4 * ty + r][n0 + 4 * tx]) = v;
    }
}

// ---------------------------------------------------------------------------
// Stage 2: combine shifts + b1 into RA/RB (+masked parts for fixup) and row
// sums SA/SB. One block per row i, 256 threads (one per hidden channel).
// ---------------------------------------------------------------------------
__global__ __launch_bounds__(256) void combine_kernel(const float* __restrict__ b1)
{
    __shared__ float smA[8], smB[8];
    const int i = blockIdx.x, h = threadIdx.x;
    const int lane = h & 31, w = h >> 5;

    float a0  = g_T[0][i][h];
    float a1m = (i > 0)      ? g_T[0][i - 1][256 + h] : 0.f;
    float a2p = (i < NN - 1) ? g_T[0][i + 1][512 + h] : 0.f;
    float ra  = a0 + b1[h] + a1m + a2p;
    g_A1M[i * HH + h] = a1m;
    g_A2P[i * HH + h] = a2p;
    g_RA [i * HH + h] = ra;

    float b0  = g_T[1][i][h];
    float b1p = (i < NN - 1) ? g_T[1][i + 1][256 + h] : 0.f;
    float b2m = (i > 0)      ? g_T[1][i - 1][512 + h] : 0.f;
    float rb  = b0 + b1p + b2m;
    g_B1P[i * HH + h] = b1p;
    g_B2M[i * HH + h] = b2m;
    g_RB [i * HH + h] = rb;

    float sa = ra, sb = rb;
#pragma unroll
    for (int off = 16; off > 0; off >>= 1) {
        sa += __shfl_xor_sync(0xffffffffu, sa, off);
        sb += __shfl_xor_sync(0xffffffffu, sb, off);
    }
    if (lane == 0) { smA[w] = sa; smB[w] = sb; }
    __syncthreads();
    if (h == 0) {
        float ta = 0.f, tb = 0.f;
#pragma unroll
        for (int k = 0; k < 8; k++) { ta += smA[k]; tb += smB[k]; }
        g_SA[i] = ta; g_SB[i] = tb;
    }
}

// ---------------------------------------------------------------------------
// Scalar epilogue used by fixup only.
// ---------------------------------------------------------------------------
__device__ __forceinline__ float ln_celu_dot(
    const float* s, const float* gm, const float* bt, const float* w2)
{
    float sum = ((s[0] + s[1]) + (s[2] + s[3])) + ((s[4] + s[5]) + (s[6] + s[7]));
    float sq0 = fmaf(s[0], s[0], s[1] * s[1]);
    sq0 = fmaf(s[2], s[2], fmaf(s[3], s[3], sq0));
    float sq1 = fmaf(s[4], s[4], s[5] * s[5]);
    sq1 = fmaf(s[6], s[6], fmaf(s[7], s[7], sq1));
    float sq = sq0 + sq1;
#pragma unroll
    for (int off = 16; off > 0; off >>= 1) {
        sum += __shfl_xor_sync(0xffffffffu, sum, off);
        sq  += __shfl_xor_sync(0xffffffffu, sq,  off);
    }
    float mu  = sum * (1.f / 256.f);
    float var = fmaf(sq, 1.f / 256.f, -mu * mu);
    float rs  = rsqrtf(var + EPSF);
    float nm  = -mu * rs;
    float acc = 0.f;
#pragma unroll
    for (int k = 0; k < 8; k++) {
        float hn = fmaf(fmaf(s[k], rs, nm), gm[k], bt[k]);
        float e  = __expf(fminf(hn, 0.f)) - 1.f;
        float v  = fmaxf(hn, 0.f) + e;
        acc = fmaf(v, w2[k], acc);
    }
#pragma unroll
    for (int off = 16; off > 0; off >>= 1)
        acc += __shfl_xor_sync(0xffffffffu, acc, off);
    return acc;
}

// ---------------------------------------------------------------------------
// Stage 3: main pairwise kernel, f32x2-packed. Warp per cell, 8 ch/lane.
// s = RA[i]+RB[j]; mean from SA/SB; variance via packed sq + 5-shfl tree;
// CELU in log2e domain: h' = t*(g*L2E)+(b*L2E); e = ex2(min(h',0));
// y = sum w2m*max(h',0) + sum w2*e  - sum(w2) + b2.
// ---------------------------------------------------------------------------
__global__ __launch_bounds__(256) void pair_main_kernel(
    const float* __restrict__ gamma, const float* __restrict__ beta,
    const float* __restrict__ W2, const float* __restrict__ b2,
    float* __restrict__ out)
{
    __shared__ float4 sA[16 * 64];
    __shared__ float4 sB[16 * 64];
    __shared__ float  sSA[16], sSB[16], sOut[256];

    const int t  = threadIdx.x;
    const int i0 = blockIdx.y * 16, j0 = blockIdx.x * 16;

    const float4* gA = reinterpret_cast<const float4*>(g_RA) + i0 * 64;
    const float4* gB = reinterpret_cast<const float4*>(g_RB) + j0 * 64;
#pragma unroll
    for (int k = 0; k < 4; k++) {
        sA[t + 256 * k] = gA[t + 256 * k];
        sB[t + 256 * k] = gB[t + 256 * k];
    }
    if (t < 16)                 sSA[t]      = g_SA[i0 + t];
    else if (t < 32)            sSB[t - 16] = g_SB[j0 + t - 16];

    const int lane = t & 31, w = t >> 5;
    const int c0 = 4 * lane, c1 = 128 + 4 * lane;
    const float L2E  = 1.4426950408889634f;
    const float IL2E = 0.6931471805599453f;   // 1/L2E = ln2

    // per-lane packed constants
    u64 g2[4], be2[4], wm2[4], we2[4];
    float w2loc;
    {
        float4 gv0 = *reinterpret_cast<const float4*>(gamma + c0);
        float4 gv1 = *reinterpret_cast<const float4*>(gamma + c1);
        float4 bv0 = *reinterpret_cast<const float4*>(beta  + c0);
        float4 bv1 = *reinterpret_cast<const float4*>(beta  + c1);
        float4 wv0 = *reinterpret_cast<const float4*>(W2    + c0);
        float4 wv1 = *reinterpret_cast<const float4*>(W2    + c1);
        g2 [0] = pk(gv0.x * L2E, gv0.y * L2E);  g2 [1] = pk(gv0.z * L2E, gv0.w * L2E);
        g2 [2] = pk(gv1.x * L2E, gv1.y * L2E);  g2 [3] = pk(gv1.z * L2E, gv1.w * L2E);
        be2[0] = pk(bv0.x * L2E, bv0.y * L2E);  be2[1] = pk(bv0.z * L2E, bv0.w * L2E);
        be2[2] = pk(bv1.x * L2E, bv1.y * L2E);  be2[3] = pk(bv1.z * L2E, bv1.w * L2E);
        wm2[0] = pk(wv0.x * IL2E, wv0.y * IL2E); wm2[1] = pk(wv0.z * IL2E, wv0.w * IL2E);
        wm2[2] = pk(wv1.x * IL2E, wv1.y * IL2E); wm2[3] = pk(wv1.z * IL2E, wv1.w * IL2E);
        we2[0] = pk(wv0.x, wv0.y);  we2[1] = pk(wv0.z, wv0.w);
        we2[2] = pk(wv1.x, wv1.y);  we2[3] = pk(wv1.z, wv1.w);
        w2loc = ((wv0.x + wv0.y) + (wv0.z + wv0.w)) + ((wv1.x + wv1.y) + (wv1.z + wv1.w));
    }
#pragma unroll
    for (int off = 16; off > 0; off >>= 1)
        w2loc += __shfl_xor_sync(0xffffffffu, w2loc, off);
    const float CADD = b2[0] - w2loc;     // -(sum of all 256 w2) + b2
    __syncthreads();

    const ulonglong2* uA = reinterpret_cast<const ulonglong2*>(sA);
    const ulonglong2* uB = reinterpret_cast<const ulonglong2*>(sB);

#pragma unroll 2
    for (int k = 0; k < 32; k++) {
        int cidx = k * 8 + w;
        int li = cidx >> 4, lj = cidx & 15;
        ulonglong2 au0 = uA[li * 64 + lane];
        ulonglong2 au1 = uA[li * 64 + 32 + lane];
        ulonglong2 bu0 = uB[lj * 64 + lane];
        ulonglong2 bu1 = uB[lj * 64 + 32 + lane];
        u64 s2[4];
        s2[0] = add2(au0.x, bu0.x);
        s2[1] = add2(au0.y, bu0.y);
        s2[2] = add2(au1.x, bu1.x);
        s2[3] = add2(au1.y, bu1.y);

        // packed sum of squares
        u64 sq2 = mul2(s2[0], s2[0]);
        sq2 = fma2(s2[1], s2[1], sq2);
        sq2 = fma2(s2[2], s2[2], sq2);
        sq2 = fma2(s2[3], s2[3], sq2);
        float sql, sqh; unpk(sq2, sql, sqh);
        float sq = sql + sqh;
#pragma unroll
        for (int off = 16; off > 0; off >>= 1)
            sq += __shfl_xor_sync(0xffffffffu, sq, off);

        float sum = sSA[li] + sSB[lj];
        float mu  = sum * (1.f / 256.f);
        float var = fmaf(sq, 1.f / 256.f, -mu * mu);
        float rs  = rsqrtf(var + EPSF);
        float nm  = -mu * rs;
        u64 rs2 = pk(rs, rs), nm2 = pk(nm, nm);

        u64 accm = 0, acce = 0;  // zero bits == (0.f,0.f)
#pragma unroll
        for (int p = 0; p < 4; p++) {
            u64 t2 = fma2(s2[p], rs2, nm2);
            u64 h2 = fma2(t2, g2[p], be2[p]);     // hn * log2(e), packed
            float hl, hh; unpk(h2, hl, hh);
            float e0 = ex2f(fminf(hl, 0.f));
            float e1 = ex2f(fminf(hh, 0.f));
            float m0 = fmaxf(hl, 0.f);
            float m1 = fmaxf(hh, 0.f);
            accm = fma2(pk(m0, m1), wm2[p], accm);
            acce = fma2(pk(e0, e1), we2[p], acce);
        }
        float aml, amh, ael, aeh;
        unpk(accm, aml, amh); unpk(acce, ael, aeh);
        float acc = (aml + amh) + (ael + aeh);
#pragma unroll
        for (int off = 16; off > 0; off >>= 1)
            acc += __shfl_xor_sync(0xffffffffu, acc, off);
        if (lane == 0) sOut[cidx] = acc + CADD;
    }
    __syncthreads();
    out[(i0 + (t >> 4)) * NN + j0 + (t & 15)] = sOut[t];
}

// ---------------------------------------------------------------------------
// Stage 4: border fixup (2044 cells), full masked formula.
// ---------------------------------------------------------------------------
__global__ __launch_bounds__(256) void fixup_kernel(
    const float* __restrict__ gamma, const float* __restrict__ beta,
    const float* __restrict__ W2, const float* __restrict__ b2,
    float* __restrict__ out)
{
    const int gw   = (blockIdx.x * 256 + threadIdx.x) >> 5;  // 0..2047
    const int lane = threadIdx.x & 31;
    const int side = gw >> 9, pos = gw & 511;
    int i, j;
    if      (side == 0) { i = 0;      j = pos; }
    else if (side == 1) { i = NN - 1; j = pos; }
    else if (side == 2) { i = pos;    j = 0; }
    else                { i = pos;    j = NN - 1; }

    const float cu = (i == 0 || j == NN - 1) ? 1.f : 0.f;
    const float cd = (i == NN - 1 || j == 0) ? 1.f : 0.f;
    const int c0 = 4 * lane, c1 = 128 + 4 * lane;

    float s[8], gm[8], bt[8], w2r[8];
#pragma unroll
    for (int k = 0; k < 8; k++) {
        int c = (k < 4) ? (c0 + k) : (c1 + k - 4);
        float ra  = g_RA [i * HH + c], rb  = g_RB [j * HH + c];
        float a1v = g_A1M[i * HH + c], b1p = g_B1P[j * HH + c];
        float a2v = g_A2P[i * HH + c], b2m = g_B2M[j * HH + c];
        s[k] = ra + rb - cu * (a1v + b1p) - cd * (a2v + b2m);
        gm[k] = gamma[c]; bt[k] = beta[c]; w2r[k] = W2[c];
    }
    float y = ln_celu_dot(s, gm, bt, w2r);
    if (lane == 0) out[i * NN + j] = y + b2[0];
}

// ---------------------------------------------------------------------------
extern "C" void kernel_launch(void* const* d_in, const int* in_sizes, int n_in,
                              void* d_out, int out_size)
{
    const float* xl    = (const float*)d_in[0];
    const float* xr    = (const float*)d_in[1];
    const float* W1    = (const float*)d_in[2];
    const float* b1    = (const float*)d_in[3];
    const float* gamma = (const float*)d_in[4];
    const float* beta  = (const float*)d_in[5];
    const float* W2    = (const float*)d_in[6];
    const float* b2    = (const float*)d_in[7];
    float* out = (float*)d_out;

    dim3 gpre(8, 12, 2);
    gemm_pre_kernel<<<gpre, 256>>>(xl, xr, W1);
    combine_kernel<<<NN, 256>>>(b1);
    dim3 grid(NN / 16, NN / 16);
    pair_main_kernel<<<grid, 256>>>(gamma, beta, W2, b2, out);
    fixup_kernel<<<(4 * NN * 32) / 256, 256>>>(gamma, beta, W2, b2, out);
}